// round 6
// baseline (speedup 1.0000x reference)
#include <cuda_runtime.h>

// Haar level-1 high-pass: out = x - mean(2x2 block), x shape (8, 64, 512, 512) fp32.
// Flattened: rows of W=512 floats, R = 262144 rows. Unit = one row-pair x 4 cols
// (two float4 loads, two float4 stores).
//
// Persistent grid-stride variant: exactly one wave of CTAs (148 SMs x 8 blocks),
// each thread loops over units. Eliminates ~55 wave transitions and block-launch
// churn; unroll-2 keeps 4 independent 16B loads in flight per thread.

static constexpr int W      = 512;
static constexpr int W4     = W / 4;           // 128 float4 per row
static constexpr int ROWS   = 8 * 64 * 512;    // 262144 rows
static constexpr int NUNITS = (ROWS / 2) * W4; // 16,777,216 units

static constexpr int TPB     = 256;
static constexpr int NBLOCKS = 148 * 8;        // one full wave at occ=8

__global__ void __launch_bounds__(TPB) fastwt_high_kernel(
    const float4* __restrict__ in, float4* __restrict__ out)
{
    const int stride = gridDim.x * blockDim.x;
    #pragma unroll 2
    for (int idx = blockIdx.x * blockDim.x + threadIdx.x; idx < NUNITS; idx += stride) {
        int cw      = idx & (W4 - 1);     // column group 0..127
        int rowpair = idx >> 7;           // idx / 128

        int i0 = rowpair * (2 * W4) + cw; // float4 index, row 2r
        int i1 = i0 + W4;                 // row 2r+1

        float4 a = in[i0];
        float4 b = in[i1];

        float m0 = (a.x + a.y + b.x + b.y) * 0.25f;
        float m1 = (a.z + a.w + b.z + b.w) * 0.25f;

        float4 o0 = make_float4(a.x - m0, a.y - m0, a.z - m1, a.w - m1);
        float4 o1 = make_float4(b.x - m0, b.y - m0, b.z - m1, b.w - m1);

        out[i0] = o0;
        out[i1] = o1;
    }
}

extern "C" void kernel_launch(void* const* d_in, const int* in_sizes, int n_in,
                              void* d_out, int out_size)
{
    const float4* in  = (const float4*)d_in[0];
    float4*       out = (float4*)d_out;
    fastwt_high_kernel<<<NBLOCKS, TPB>>>(in, out);
}

// round 7
// speedup vs baseline: 1.0977x; 1.0977x over previous
#include <cuda_runtime.h>

// Haar level-1 high-pass: out = x - mean(2x2 block), x shape (8, 64, 512, 512) fp32.
// Flattened view: rows of length W=512, total rows R = 8*64*512 = 262144.
// Each thread: one row-pair (2r, 2r+1) x 4 columns => two float4 loads, two float4 stores.
//
// FINAL (measured optimum): ~6.86 TB/s, 86.6% DRAM-active — at the B300 mixed
// read/write streaming ceiling. Explored and rejected with measurements:
//   - v8.f32 256-bit ld/st:        neutral (LSU was never the limiter)
//   - __ldcs/__stcs streaming:     neutral (touch-once already behaves streaming)
//   - TPB=512:                     neutral
//   - persistent grid-stride:      -12% (serializes MLP; flat short-lived warps
//                                   give the scheduler maximal independent loads)
// Traffic is provably minimal (1 GiB touch-once, no reuse, fp32 mandated).

static constexpr int W      = 512;
static constexpr int W4     = W / 4;           // 128 float4 per row
static constexpr int ROWS   = 8 * 64 * 512;    // 262144 rows
static constexpr int NUNITS = (ROWS / 2) * W4; // 16,777,216 thread-units

__global__ void __launch_bounds__(256) fastwt_high_kernel(
    const float4* __restrict__ in, float4* __restrict__ out)
{
    int idx = blockIdx.x * blockDim.x + threadIdx.x;   // < NUNITS (exact grid)
    int cw      = idx & (W4 - 1);     // column group 0..127
    int rowpair = idx >> 7;           // idx / 128

    int i0 = rowpair * (2 * W4) + cw; // float4 index, row 2r
    int i1 = i0 + W4;                 // row 2r+1

    float4 a = in[i0];
    float4 b = in[i1];

    float m0 = (a.x + a.y + b.x + b.y) * 0.25f;
    float m1 = (a.z + a.w + b.z + b.w) * 0.25f;

    float4 o0 = make_float4(a.x - m0, a.y - m0, a.z - m1, a.w - m1);
    float4 o1 = make_float4(b.x - m0, b.y - m0, b.z - m1, b.w - m1);

    out[i0] = o0;
    out[i1] = o1;
}

extern "C" void kernel_launch(void* const* d_in, const int* in_sizes, int n_in,
                              void* d_out, int out_size)
{
    const float4* in  = (const float4*)d_in[0];
    float4*       out = (float4*)d_out;
    constexpr int TPB = 256;
    fastwt_high_kernel<<<NUNITS / TPB, TPB>>>(in, out);
}

// round 9
// speedup vs baseline: 1.0990x; 1.0012x over previous
#include <cuda_runtime.h>

// Haar level-1 high-pass: out = x - mean(2x2 block), x shape (8, 64, 512, 512) fp32.
// Flattened: rows of W=512 floats, R = 262144 rows.
// Variant: each thread owns a 4-row x 4-col tile (two vertical 2x2 block-rows):
// 4 independent float4 loads issued back-to-back (MLP_p1=4), then compute, then
// 4 float4 stores. Tests whether deeper per-thread load batching beats the
// 2-load baseline (148.4us, 86.7% DRAM) at the streaming wall.

static constexpr int W      = 512;
static constexpr int W4     = W / 4;           // 128 float4 per row
static constexpr int ROWS   = 8 * 64 * 512;    // 262144 rows
static constexpr int NUNITS = (ROWS / 4) * W4; // 8,388,608 thread-units

__global__ void __launch_bounds__(256) fastwt_high_kernel(
    const float4* __restrict__ in, float4* __restrict__ out)
{
    int idx = blockIdx.x * blockDim.x + threadIdx.x;   // < NUNITS (exact grid)
    int cw      = idx & (W4 - 1);     // column group 0..127
    int rowquad = idx >> 7;           // idx / 128 -> rows 4r..4r+3

    int i0 = rowquad * (4 * W4) + cw; // row 4r
    int i1 = i0 + W4;                 // row 4r+1
    int i2 = i1 + W4;                 // row 4r+2
    int i3 = i2 + W4;                 // row 4r+3

    // Front-batched independent loads (MLP_p1 = 4)
    float4 a = in[i0];
    float4 b = in[i1];
    float4 c = in[i2];
    float4 d = in[i3];

    // Block-row 0: rows (4r, 4r+1)
    float m0 = (a.x + a.y + b.x + b.y) * 0.25f;
    float m1 = (a.z + a.w + b.z + b.w) * 0.25f;
    // Block-row 1: rows (4r+2, 4r+3)
    float m2 = (c.x + c.y + d.x + d.y) * 0.25f;
    float m3 = (c.z + c.w + d.z + d.w) * 0.25f;

    out[i0] = make_float4(a.x - m0, a.y - m0, a.z - m1, a.w - m1);
    out[i1] = make_float4(b.x - m0, b.y - m0, b.z - m1, b.w - m1);
    out[i2] = make_float4(c.x - m2, c.y - m2, c.z - m3, c.w - m3);
    out[i3] = make_float4(d.x - m2, d.y - m2, d.z - m3, d.w - m3);
}

extern "C" void kernel_launch(void* const* d_in, const int* in_sizes, int n_in,
                              void* d_out, int out_size)
{
    const float4* in  = (const float4*)d_in[0];
    float4*       out = (float4*)d_out;
    constexpr int TPB = 256;
    fastwt_high_kernel<<<NUNITS / TPB, TPB>>>(in, out);
}

// round 10
// speedup vs baseline: 1.1006x; 1.0014x over previous
#include <cuda_runtime.h>

// Haar level-1 high-pass: out = x - mean(2x2 block), x shape (8, 64, 512, 512) fp32.
// Flattened view: rows of length W=512, total rows R = 8*64*512 = 262144.
// Each thread: one row-pair (2r, 2r+1) x 4 columns => two float4 loads, two float4 stores.
//
// FINAL (measured optimum across 6 hardware rounds): 148.4us kernel, 6.87 TB/s,
// 86.7% DRAM-active — the B300 mixed read/write streaming ceiling.
// Measured and rejected:
//   - v8.f32 256-bit ld/st:    neutral (LSU/wavefront path never the limiter)
//   - __ldcs/__stcs streaming: neutral (touch-once already streams)
//   - TPB=512:                 neutral
//   - persistent grid-stride:  -12% (serializes per-thread MLP; flat short-lived
//                              warps give the scheduler maximal independent loads)
//   - 4-load front-batched tile: neutral (~-0.7%, spread penalty offsets MLP gain)
// Traffic is provably minimal: 512 MiB read + 512 MiB write, zero reuse,
// fp32 output mandated. HBM-bound at the roofline.

static constexpr int W      = 512;
static constexpr int W4     = W / 4;           // 128 float4 per row
static constexpr int ROWS   = 8 * 64 * 512;    // 262144 rows
static constexpr int NUNITS = (ROWS / 2) * W4; // 16,777,216 thread-units

__global__ void __launch_bounds__(256) fastwt_high_kernel(
    const float4* __restrict__ in, float4* __restrict__ out)
{
    int idx = blockIdx.x * blockDim.x + threadIdx.x;   // < NUNITS (exact grid)
    int cw      = idx & (W4 - 1);     // column group 0..127
    int rowpair = idx >> 7;           // idx / 128

    int i0 = rowpair * (2 * W4) + cw; // float4 index, row 2r
    int i1 = i0 + W4;                 // row 2r+1

    float4 a = in[i0];
    float4 b = in[i1];

    float m0 = (a.x + a.y + b.x + b.y) * 0.25f;
    float m1 = (a.z + a.w + b.z + b.w) * 0.25f;

    float4 o0 = make_float4(a.x - m0, a.y - m0, a.z - m1, a.w - m1);
    float4 o1 = make_float4(b.x - m0, b.y - m0, b.z - m1, b.w - m1);

    out[i0] = o0;
    out[i1] = o1;
}

extern "C" void kernel_launch(void* const* d_in, const int* in_sizes, int n_in,
                              void* d_out, int out_size)
{
    const float4* in  = (const float4*)d_in[0];
    float4*       out = (float4*)d_out;
    constexpr int TPB = 256;
    fastwt_high_kernel<<<NUNITS / TPB, TPB>>>(in, out);
}